// round 12
// baseline (speedup 1.0000x reference)
#include <cuda_runtime.h>

// LambdaRankLoss N=8192, 5 integer classes (0..4), SIGMA=1.
//
//   e = exp(p), g = 2^t, d = 1/log2(rank+1), rank = stable ascending-by-target.
//   lambda_i = scale * ( e_i * T1_i - T2_i ),  scale = 1/maxDCG
//   T1_i = sum_c (G_c - g_i) * sum_{j in c} (d_i - d_j) r_ij,  r = 1/(e_i+e_j)
//   T2_i = sum_{c < v_i} (G_c - g_i)(n_c d_i - SD_c)     [O(1), reduce]
//
// CLASS-ALIGNED PADDING (pad e=1e18 finite): each 128-j tile single-class ->
// static trip counts. RCP-MERGE: rp=rcp(s0*s1) serves both rows (1 MUFU/2 pairs).
// Grid 35x35 (256 rows x 256 j per block) -> 1225 blocks = single wave, no tail.

#define N      8192
#define K_DCG  512
#define NT     70            // 128-wide class-aligned j tiles
#define NPAD   (NT * 128)    // 8960
#define SB     35            // j superblocks (256 j each) == row superblocks
#define RBLK   256
#define PAIR_T 128
#define PBLK   32
#define PADE   1.0e18f

__device__ float2 g_sed[NPAD];       // padded-sorted (e, -decay); pad = (1e18, 0)
__device__ int    g_inv[NPAD];       // padded pos -> original index; pad = -1
__device__ int    g_seg[8];          // TRUE class segment bounds
__device__ int    g_pbase[8];        // PADDED class segment bases
__device__ float  g_tGc[NT];         // per-tile class gain 2^c; 0.0 = all-pad tile
__device__ int    g_wpre[256][8];    // per-32-chunk exclusive prefix (padded pos math)
__device__ float  g_pSD[PBLK][5];
__device__ float  g_pDCG[PBLK];
__device__ float2 g_part[SB][NPAD / 2];

__device__ __forceinline__ float frcp(float x) {
    float r;
    asm("rcp.approx.f32 %0, %1;" : "=f"(r) : "f"(x));
    return r;
}

// ---------------- prep A: fused count + scan (single block, alu-only) ------
__global__ void __launch_bounds__(256)
prep_cscan(const float* __restrict__ tgt) {
    __shared__ int s[5][256];
    __shared__ int s_base[6];

    const int t = threadIdx.x;

    // clear padded arrays (scatter overwrites real slots)
    const float2 padval = make_float2(PADE, 0.0f);
    for (int i = t; i < NPAD; i += 256) {
        g_sed[i] = padval;
        g_inv[i] = -1;
    }

    // count 32 consecutive elements (chunk == original 32-aligned warp chunk)
    int loc[5] = {0, 0, 0, 0, 0};
    const float4* __restrict__ tp = (const float4*)(tgt + t * 32);
    #pragma unroll
    for (int k = 0; k < 8; k++) {
        float4 v4 = __ldg(tp + k);
        int c0 = max(0, min(4, (int)v4.x));
        int c1 = max(0, min(4, (int)v4.y));
        int c2 = max(0, min(4, (int)v4.z));
        int c3 = max(0, min(4, (int)v4.w));
        loc[c0]++; loc[c1]++; loc[c2]++; loc[c3]++;
    }
    int own[5];
    #pragma unroll
    for (int c = 0; c < 5; c++) { own[c] = loc[c]; s[c][t] = loc[c]; }
    __syncthreads();

    // Hillis-Steele inclusive scan over 256 chunks, per class
    for (int ofs = 1; ofs < 256; ofs <<= 1) {
        int a[5] = {0, 0, 0, 0, 0};
        if (t >= ofs) {
            #pragma unroll
            for (int c = 0; c < 5; c++) a[c] = s[c][t - ofs];
        }
        __syncthreads();
        #pragma unroll
        for (int c = 0; c < 5; c++) s[c][t] += a[c];
        __syncthreads();
    }

    if (t == 0) {
        int run = 0, prun = 0;
        int pb[6];
        #pragma unroll
        for (int c = 0; c < 5; c++) {
            int nc = s[c][255];
            s_base[c]  = run;
            g_seg[c]   = run;
            pb[c]      = prun;
            g_pbase[c] = prun;
            run  += nc;
            prun += ((nc + 127) / 128) * 128;
        }
        g_seg[5]   = N;
        pb[5]      = prun;
        g_pbase[5] = prun;
        for (int tl = 0; tl < NT; tl++) {
            int start = tl * 128;
            float gc = 0.0f;                      // 0 = all-pad tile (skipped)
            #pragma unroll
            for (int c = 0; c < 5; c++)
                if (start >= pb[c] && start < pb[c + 1]) gc = (float)(1 << c);
            g_tGc[tl] = gc;
        }
    }
    __syncthreads();

    #pragma unroll
    for (int c = 0; c < 5; c++)
        g_wpre[t][c] = s_base[c] + s[c][t] - own[c];       // exclusive (true pos)
}

// ---------------- prep B: scatter to PADDED sorted order + SD/DCG ----------
__global__ void __launch_bounds__(256)
prep_scatter(const float* __restrict__ pred, const float* __restrict__ tgt) {
    __shared__ float s_sd[8][5];
    __shared__ float s_dcg[8];

    const int i    = blockIdx.x * 256 + threadIdx.x;
    const int lane = threadIdx.x & 31;
    const int wid  = threadIdx.x >> 5;
    const int gw   = i >> 5;

    int v = (int)tgt[i];
    v = max(0, min(4, v));

    int intra = 0;
    #pragma unroll
    for (int c = 0; c < 5; c++) {
        unsigned b = __ballot_sync(0xffffffffu, v == c);
        if (v == c) intra = __popc(b & ((1u << lane) - 1u));
    }
    const int k  = g_wpre[gw][v] + intra;                  // TRUE sorted pos
    const int kp = g_pbase[v] + (k - g_seg[v]);            // PADDED pos

    const float e = __expf(pred[i]);
    const float d = __fdividef(1.0f, log2f((float)k + 2.0f));
    g_sed[kp] = make_float2(e, -d);
    g_inv[kp] = i;

    float term = 0.0f;
    if (k >= N - K_DCG) {
        int r = N - k;                                     // descending rank
        term = (exp2f((float)v) - 1.0f) / log2f((float)r + 1.0f);
    }

    #pragma unroll
    for (int c = 0; c < 5; c++) {
        float x = (v == c) ? d : 0.0f;
        #pragma unroll
        for (int o = 16; o > 0; o >>= 1)
            x += __shfl_down_sync(0xffffffffu, x, o);
        if (lane == 0) s_sd[wid][c] = x;
    }
    {
        float x = term;
        #pragma unroll
        for (int o = 16; o > 0; o >>= 1)
            x += __shfl_down_sync(0xffffffffu, x, o);
        if (lane == 0) s_dcg[wid] = x;
    }
    __syncthreads();

    if (threadIdx.x < 5) {
        float s = 0.0f;
        #pragma unroll
        for (int w = 0; w < 8; w++) s += s_sd[w][threadIdx.x];
        g_pSD[blockIdx.x][threadIdx.x] = s;
    } else if (threadIdx.x == 5) {
        float s = 0.0f;
        #pragma unroll
        for (int w = 0; w < 8; w++) s += s_dcg[w];
        g_pDCG[blockIdx.x] = s;
    }
}

// ---------------- pairwise: grid (SB, SB); 2 class-tiles per block ---------
__global__ void __launch_bounds__(PAIR_T)
pair_kernel() {
    const int t  = threadIdx.x;
    const int r0 = blockIdx.x * RBLK + 2 * t;
    const int r1 = r0 + 1;

    const int pb1 = g_pbase[1], pb2 = g_pbase[2],
              pb3 = g_pbase[3], pb4 = g_pbase[4];

    const float2 a0 = g_sed[r0];
    const float2 a1 = g_sed[r1];
    const float e0 = a0.x, d0 = -a0.y;
    const float e1 = a1.x, d1 = -a1.y;
    const float gi0 = (float)(1 << ((r0 >= pb1) + (r0 >= pb2) + (r0 >= pb3) + (r0 >= pb4)));
    const float gi1 = (float)(1 << ((r1 >= pb1) + (r1 >= pb2) + (r1 >= pb3) + (r1 >= pb4)));

    float acc0 = 0.0f, acc1 = 0.0f;

    #pragma unroll
    for (int ch = 0; ch < 2; ch++) {
        const int tile = blockIdx.y * 2 + ch;
        const float Gc = g_tGc[tile];
        if (Gc == 0.0f) continue;                  // all-pad tile (block-uniform)
        const float coef0 = Gc - gi0;
        const float coef1 = Gc - gi1;
        if (__all_sync(0xffffffffu, (coef0 == 0.0f) && (coef1 == 0.0f))) continue;

        const float4* __restrict__ p = (const float4*)(g_sed + tile * 128);

        float A0a = 0.f, A0b = 0.f, A1a = 0.f, A1b = 0.f;

        #pragma unroll 8
        for (int j = 0; j < 64; j++) {
            const float4 w = __ldg(p + j);         // (e_a, nd_a, e_b, nd_b)
            {
                float s0  = e0 + w.x;
                float s1  = e1 + w.x;
                float rp  = frcp(s0 * s1);          // one MUFU for both rows
                float dd0 = d0 + w.y;
                float dd1 = d1 + w.y;
                A0a = fmaf(dd0, rp * s1, A0a);
                A1a = fmaf(dd1, rp * s0, A1a);
            }
            {
                float s0  = e0 + w.z;
                float s1  = e1 + w.z;
                float rp  = frcp(s0 * s1);
                float dd0 = d0 + w.w;
                float dd1 = d1 + w.w;
                A0b = fmaf(dd0, rp * s1, A0b);
                A1b = fmaf(dd1, rp * s0, A1b);
            }
        }
        acc0 = fmaf(coef0, A0a + A0b, acc0);
        acc1 = fmaf(coef1, A1a + A1b, acc1);
    }

    g_part[blockIdx.y][blockIdx.x * (RBLK / 2) + t] = make_float2(acc0, acc1);
}

// ---------------- reduce: finish SD/DCG, T1 + analytic T2, scatter ---------
__global__ void __launch_bounds__(256)
reduce_kernel(float* __restrict__ out) {
    __shared__ float s_scale;
    __shared__ float s_SD[5];

    const int t    = threadIdx.x;
    const int lane = t & 31;
    const int wid  = t >> 5;

    if (wid == 0) {
        float x = g_pDCG[lane];                    // PBLK == 32
        #pragma unroll
        for (int o = 16; o > 0; o >>= 1)
            x += __shfl_down_sync(0xffffffffu, x, o);
        if (lane == 0) s_scale = __fdividef(1.0f, x);
    } else if (wid <= 5) {
        float x = g_pSD[lane][wid - 1];
        #pragma unroll
        for (int o = 16; o > 0; o >>= 1)
            x += __shfl_down_sync(0xffffffffu, x, o);
        if (lane == 0) s_SD[wid - 1] = x;
    }
    __syncthreads();

    const int kp  = blockIdx.x * 256 + t;          // padded position
    const int idx = g_inv[kp];
    if (idx < 0) return;                           // padding slot

    float T1 = 0.0f;
    #pragma unroll
    for (int s = 0; s < SB; s++)
        T1 += ((const float*)g_part[s])[kp];

    const int pb1 = g_pbase[1], pb2 = g_pbase[2],
              pb3 = g_pbase[3], pb4 = g_pbase[4];
    const int v = (kp >= pb1) + (kp >= pb2) + (kp >= pb3) + (kp >= pb4);

    const float2 a = g_sed[kp];
    const float e = a.x;
    const float d = -a.y;
    const float g = (float)(1 << v);

    float T2 = 0.0f;
    #pragma unroll
    for (int c = 0; c < 4; c++) {
        if (c < v) {
            float nc = (float)(g_seg[c + 1] - g_seg[c]);
            T2 += ((float)(1 << c) - g) * (nc * d - s_SD[c]);
        }
    }

    out[idx] = s_scale * (e * T1 - T2);
}

extern "C" void kernel_launch(void* const* d_in, const int* in_sizes, int n_in,
                              void* d_out, int out_size) {
    const float* pred = (const float*)d_in[0];
    const float* tgt  = (const float*)d_in[1];
    float* out        = (float*)d_out;

    prep_cscan<<<1, 256>>>(tgt);
    prep_scatter<<<PBLK, 256>>>(pred, tgt);
    dim3 grid(SB, SB);
    pair_kernel<<<grid, PAIR_T>>>();
    reduce_kernel<<<NPAD / 256, 256>>>(out);
}

// round 13
// speedup vs baseline: 1.1290x; 1.1290x over previous
#include <cuda_runtime.h>

// LambdaRankLoss N=8192, 5 integer classes (0..4), SIGMA=1.
//
//   e = exp(p), g = 2^t, d = 1/log2(rank+1), rank = stable ascending-by-target.
//   lambda_i = scale * ( e_i * T1_i - T2_i ),  scale = 1/maxDCG
//   T1_i = sum_c (G_c - g_i) * sum_{j in c} (d_i - d_j) r_ij,  r = 1/(e_i+e_j)
//   T2_i = sum_{c < v_i} (G_c - g_i)(n_c d_i - SD_c)     [O(1), reduce]
//
// CLASS-ALIGNED PADDING (pad e=1e18 finite): each 128-j tile single-class ->
// static trip counts. RCP-MERGE: rp=rcp(s0*s1) serves both rows (1 MUFU/2 pairs).
// Pair grid (35 row-blocks x 70 tiles); reduce uses 4 threads per position.

#define N      8192
#define K_DCG  512
#define NT     70            // 128-wide class-aligned j tiles
#define NPAD   (NT * 128)    // 8960
#define RBLK   256
#define NRB    (NPAD / RBLK) // 35
#define PAIR_T 128
#define PBLK   32
#define PADE   1.0e18f

__device__ float2 g_sed[NPAD];       // padded-sorted (e, -decay); pad = (1e18, 0)
__device__ int    g_inv[NPAD];       // padded pos -> original index; pad = -1
__device__ int    g_seg[8];          // TRUE class segment bounds
__device__ int    g_pbase[8];        // PADDED class segment bases
__device__ float  g_tGc[NT];         // per-tile class gain 2^c; 0.0 = all-pad tile
__device__ int    g_wpre[256][8];    // per-32-chunk exclusive prefix
__device__ float  g_pSD[PBLK][5];
__device__ float  g_pDCG[PBLK];
__device__ float2 g_part[NT][NPAD / 2];

__device__ __forceinline__ float frcp(float x) {
    float r;
    asm("rcp.approx.f32 %0, %1;" : "=f"(r) : "f"(x));
    return r;
}

// ---------------- prep A: fused count + scan (single block, alu-only) ------
__global__ void __launch_bounds__(256)
prep_cscan(const float* __restrict__ tgt) {
    __shared__ int s[5][256];
    __shared__ int s_base[6];

    const int t = threadIdx.x;

    const float2 padval = make_float2(PADE, 0.0f);
    for (int i = t; i < NPAD; i += 256) {
        g_sed[i] = padval;
        g_inv[i] = -1;
    }

    int loc[5] = {0, 0, 0, 0, 0};
    const float4* __restrict__ tp = (const float4*)(tgt + t * 32);
    #pragma unroll
    for (int k = 0; k < 8; k++) {
        float4 v4 = __ldg(tp + k);
        int c0 = max(0, min(4, (int)v4.x));
        int c1 = max(0, min(4, (int)v4.y));
        int c2 = max(0, min(4, (int)v4.z));
        int c3 = max(0, min(4, (int)v4.w));
        loc[c0]++; loc[c1]++; loc[c2]++; loc[c3]++;
    }
    int own[5];
    #pragma unroll
    for (int c = 0; c < 5; c++) { own[c] = loc[c]; s[c][t] = loc[c]; }
    __syncthreads();

    for (int ofs = 1; ofs < 256; ofs <<= 1) {
        int a[5] = {0, 0, 0, 0, 0};
        if (t >= ofs) {
            #pragma unroll
            for (int c = 0; c < 5; c++) a[c] = s[c][t - ofs];
        }
        __syncthreads();
        #pragma unroll
        for (int c = 0; c < 5; c++) s[c][t] += a[c];
        __syncthreads();
    }

    if (t == 0) {
        int run = 0, prun = 0;
        int pb[6];
        #pragma unroll
        for (int c = 0; c < 5; c++) {
            int nc = s[c][255];
            s_base[c]  = run;
            g_seg[c]   = run;
            pb[c]      = prun;
            g_pbase[c] = prun;
            run  += nc;
            prun += ((nc + 127) / 128) * 128;
        }
        g_seg[5]   = N;
        pb[5]      = prun;
        g_pbase[5] = prun;
        for (int tl = 0; tl < NT; tl++) {
            int start = tl * 128;
            float gc = 0.0f;                      // 0 = all-pad tile (skipped)
            #pragma unroll
            for (int c = 0; c < 5; c++)
                if (start >= pb[c] && start < pb[c + 1]) gc = (float)(1 << c);
            g_tGc[tl] = gc;
        }
    }
    __syncthreads();

    #pragma unroll
    for (int c = 0; c < 5; c++)
        g_wpre[t][c] = s_base[c] + s[c][t] - own[c];       // exclusive (true pos)
}

// ---------------- prep B: scatter to PADDED sorted order + SD/DCG ----------
__global__ void __launch_bounds__(256)
prep_scatter(const float* __restrict__ pred, const float* __restrict__ tgt) {
    __shared__ float s_sd[8][5];
    __shared__ float s_dcg[8];

    const int i    = blockIdx.x * 256 + threadIdx.x;
    const int lane = threadIdx.x & 31;
    const int wid  = threadIdx.x >> 5;
    const int gw   = i >> 5;

    int v = (int)tgt[i];
    v = max(0, min(4, v));

    int intra = 0;
    #pragma unroll
    for (int c = 0; c < 5; c++) {
        unsigned b = __ballot_sync(0xffffffffu, v == c);
        if (v == c) intra = __popc(b & ((1u << lane) - 1u));
    }
    const int k  = g_wpre[gw][v] + intra;                  // TRUE sorted pos
    const int kp = g_pbase[v] + (k - g_seg[v]);            // PADDED pos

    const float e = __expf(pred[i]);
    const float d = __fdividef(1.0f, log2f((float)k + 2.0f));
    g_sed[kp] = make_float2(e, -d);
    g_inv[kp] = i;

    float term = 0.0f;
    if (k >= N - K_DCG) {
        int r = N - k;                                     // descending rank
        term = (exp2f((float)v) - 1.0f) / log2f((float)r + 1.0f);
    }

    #pragma unroll
    for (int c = 0; c < 5; c++) {
        float x = (v == c) ? d : 0.0f;
        #pragma unroll
        for (int o = 16; o > 0; o >>= 1)
            x += __shfl_down_sync(0xffffffffu, x, o);
        if (lane == 0) s_sd[wid][c] = x;
    }
    {
        float x = term;
        #pragma unroll
        for (int o = 16; o > 0; o >>= 1)
            x += __shfl_down_sync(0xffffffffu, x, o);
        if (lane == 0) s_dcg[wid] = x;
    }
    __syncthreads();

    if (threadIdx.x < 5) {
        float s = 0.0f;
        #pragma unroll
        for (int w = 0; w < 8; w++) s += s_sd[w][threadIdx.x];
        g_pSD[blockIdx.x][threadIdx.x] = s;
    } else if (threadIdx.x == 5) {
        float s = 0.0f;
        #pragma unroll
        for (int w = 0; w < 8; w++) s += s_dcg[w];
        g_pDCG[blockIdx.x] = s;
    }
}

// ---------------- pairwise: grid (NRB, NT); static 128-trip loop -----------
__global__ void __launch_bounds__(PAIR_T)
pair_kernel() {
    const int t  = threadIdx.x;
    const int r0 = blockIdx.x * RBLK + 2 * t;
    const int r1 = r0 + 1;

    const int pb1 = g_pbase[1], pb2 = g_pbase[2],
              pb3 = g_pbase[3], pb4 = g_pbase[4];

    const float2 a0 = g_sed[r0];
    const float2 a1 = g_sed[r1];
    const float e0 = a0.x, d0 = -a0.y;
    const float e1 = a1.x, d1 = -a1.y;
    const float gi0 = (float)(1 << ((r0 >= pb1) + (r0 >= pb2) + (r0 >= pb3) + (r0 >= pb4)));
    const float gi1 = (float)(1 << ((r1 >= pb1) + (r1 >= pb2) + (r1 >= pb3) + (r1 >= pb4)));

    const float Gc    = g_tGc[blockIdx.y];
    const float coef0 = Gc - gi0;
    const float coef1 = Gc - gi1;

    float2 res = make_float2(0.0f, 0.0f);

    bool skip = (Gc == 0.0f) ||
                __all_sync(0xffffffffu, (coef0 == 0.0f) && (coef1 == 0.0f));
    if (!skip) {
        const float4* __restrict__ p = (const float4*)(g_sed + blockIdx.y * 128);

        float A0a = 0.f, A0b = 0.f, A1a = 0.f, A1b = 0.f;

        #pragma unroll 8
        for (int j = 0; j < 64; j++) {
            const float4 w = __ldg(p + j);         // (e_a, nd_a, e_b, nd_b)
            {
                float s0  = e0 + w.x;
                float s1  = e1 + w.x;
                float rp  = frcp(s0 * s1);          // one MUFU for both rows
                float dd0 = d0 + w.y;
                float dd1 = d1 + w.y;
                A0a = fmaf(dd0, rp * s1, A0a);
                A1a = fmaf(dd1, rp * s0, A1a);
            }
            {
                float s0  = e0 + w.z;
                float s1  = e1 + w.z;
                float rp  = frcp(s0 * s1);
                float dd0 = d0 + w.w;
                float dd1 = d1 + w.w;
                A0b = fmaf(dd0, rp * s1, A0b);
                A1b = fmaf(dd1, rp * s0, A1b);
            }
        }
        res.x = coef0 * (A0a + A0b);
        res.y = coef1 * (A1a + A1b);
    }

    g_part[blockIdx.y][blockIdx.x * (RBLK / 2) + t] = res;
}

// ---------------- reduce: 4 threads per position, grid 140 -----------------
__global__ void __launch_bounds__(256)
reduce_kernel(float* __restrict__ out) {
    __shared__ float s_scale;
    __shared__ float s_SD[5];

    const int t    = threadIdx.x;
    const int lane = t & 31;
    const int wid  = t >> 5;

    if (wid == 0) {
        float x = g_pDCG[lane];                    // PBLK == 32
        #pragma unroll
        for (int o = 16; o > 0; o >>= 1)
            x += __shfl_down_sync(0xffffffffu, x, o);
        if (lane == 0) s_scale = __fdividef(1.0f, x);
    } else if (wid <= 5) {
        float x = g_pSD[lane][wid - 1];
        #pragma unroll
        for (int o = 16; o > 0; o >>= 1)
            x += __shfl_down_sync(0xffffffffu, x, o);
        if (lane == 0) s_SD[wid - 1] = x;
    }
    __syncthreads();

    const int kp  = blockIdx.x * 64 + (t >> 2);    // padded position
    const int sub = t & 3;                         // slice-group id

    // 4 threads sum disjoint slice sets; fixed order -> deterministic
    float T1p = 0.0f;
    #pragma unroll
    for (int s = 0; s < NT / 4; s++)               // 17 full rounds
        T1p += ((const float*)g_part[sub + 4 * s])[kp];
    if (sub < 2)                                   // slices 68, 69
        T1p += ((const float*)g_part[68 + sub])[kp];

    // butterfly across the 4-lane group
    T1p += __shfl_xor_sync(0xffffffffu, T1p, 1);
    T1p += __shfl_xor_sync(0xffffffffu, T1p, 2);
    const float T1 = T1p;

    if (sub != 0) return;
    const int idx = g_inv[kp];
    if (idx < 0) return;                           // padding slot

    const int pb1 = g_pbase[1], pb2 = g_pbase[2],
              pb3 = g_pbase[3], pb4 = g_pbase[4];
    const int v = (kp >= pb1) + (kp >= pb2) + (kp >= pb3) + (kp >= pb4);

    const float2 a = g_sed[kp];
    const float e = a.x;
    const float d = -a.y;
    const float g = (float)(1 << v);

    float T2 = 0.0f;
    #pragma unroll
    for (int c = 0; c < 4; c++) {
        if (c < v) {
            float nc = (float)(g_seg[c + 1] - g_seg[c]);
            T2 += ((float)(1 << c) - g) * (nc * d - s_SD[c]);
        }
    }

    out[idx] = s_scale * (e * T1 - T2);
}

extern "C" void kernel_launch(void* const* d_in, const int* in_sizes, int n_in,
                              void* d_out, int out_size) {
    const float* pred = (const float*)d_in[0];
    const float* tgt  = (const float*)d_in[1];
    float* out        = (float*)d_out;

    prep_cscan<<<1, 256>>>(tgt);
    prep_scatter<<<PBLK, 256>>>(pred, tgt);
    dim3 grid(NRB, NT);
    pair_kernel<<<grid, PAIR_T>>>();
    reduce_kernel<<<NPAD / 64, 256>>>(out);
}